// round 1
// baseline (speedup 1.0000x reference)
#include <cuda_runtime.h>
#include <math.h>

#define B_  32
#define T_  1024
#define D_  256
#define U_  512
#define G3  1536          // 3*U
#define NCTA_SCAN 128

// ---------------- scratch (device globals: allocation-free contract) ----------
__device__ float g_xw[(size_t)T_ * B_ * G3];     // [T,B,3U] gate pre-activations (reused per layer)
__device__ float g_out0[(size_t)T_ * B_ * U_];   // layer-0 outputs [T,B,U]
__device__ float g_pred0[(size_t)T_ * B_ * U_];  // layer-1 outputs
__device__ float g_pred1[(size_t)T_ * B_ * U_];  // layer-2 outputs
__device__ float g_h[B_ * U_];                   // carried hidden state
__device__ unsigned g_bar_count = 0;
__device__ unsigned g_bar_gen   = 0;

// ---------------- grid-wide sense-reversing barrier ---------------------------
__device__ __forceinline__ void grid_barrier(unsigned ncta) {
    __syncthreads();
    if (threadIdx.x == 0) {
        volatile unsigned* genp = &g_bar_gen;
        unsigned g = *genp;
        __threadfence();
        unsigned arrived = atomicAdd(&g_bar_count, 1u);
        if (arrived == ncta - 1u) {
            g_bar_count = 0;
            __threadfence();
            *genp = g + 1u;
        } else {
            while (*genp == g) { }
        }
        __threadfence();
    }
    __syncthreads();
}

// ---------------- init hidden state: h[b][u] = h0[u] --------------------------
__global__ void init_h_kernel(float* __restrict__ h, const float* __restrict__ h0) {
    int i = blockIdx.x * blockDim.x + threadIdx.x;
    if (i < B_ * U_) h[i] = h0[i & (U_ - 1)];
}

// ---------------- persistent GRU scan ----------------------------------------
// 128 CTAs x 256 threads. CTA c owns hidden units u0=4c..4c+3 (12 recurrent
// columns held in SMEM for the entire scan). Warp w handles batches 4w..4w+3.
// Lane l accumulates partial dots over k = 4l+128*i2+kk.
__global__ void __launch_bounds__(256, 1) scan_kernel(
    const float* __restrict__ R,      // recurrent [U,3U]
    const float* __restrict__ brec,   // recurrent bias [3U]
    const float* __restrict__ xw,     // [T,B,3U]
    float* __restrict__ out,          // [T,B,U]
    float* __restrict__ h)            // [B,U] carried state (global)
{
    __shared__ float ws2[4 * 128 * 20];   // [k%4][k/4][12 cols + pad] (40 KB)

    const int tid = threadIdx.x;
    const int u0  = blockIdx.x * 4;

    // Preload the 12 recurrent columns this CTA owns.
    for (int idx = tid; idx < U_ * 12; idx += 256) {
        int k = idx / 12, c = idx - k * 12;
        int g = c >> 2, j = c & 3;
        ws2[(k & 3) * 2560 + (k >> 2) * 20 + c] =
            R[(size_t)k * G3 + g * U_ + u0 + j];
    }
    __syncthreads();

    const int w  = tid >> 5, l = tid & 31;
    const int b0 = w * 4;
    const int lb = l >> 2, uj = l & 3;
    const int gb = b0 + lb;          // batch handled by this gate-lane
    const int gu = u0 + uj;          // global hidden index handled
    float bz = 0.f, brr = 0.f, bh = 0.f;
    if (l < 16) {
        bz  = brec[gu];
        brr = brec[U_ + gu];
        bh  = brec[2 * U_ + gu];
    }

    for (int t = 0; t < T_; t++) {
        float acc[4][12];
        #pragma unroll
        for (int b = 0; b < 4; b++)
            #pragma unroll
            for (int c = 0; c < 12; c++) acc[b][c] = 0.f;

        #pragma unroll
        for (int i2 = 0; i2 < 4; i2++) {
            float4 hv[4];
            #pragma unroll
            for (int b = 0; b < 4; b++)
                hv[b] = __ldcg((const float4*)(h + (b0 + b) * U_ + 4 * l + 128 * i2));
            #pragma unroll
            for (int kk = 0; kk < 4; kk++) {
                const float* wp = &ws2[kk * 2560 + (l + 32 * i2) * 20];
                float4 wz = *(const float4*)(wp);
                float4 wr = *(const float4*)(wp + 4);
                float4 wh = *(const float4*)(wp + 8);
                #pragma unroll
                for (int b = 0; b < 4; b++) {
                    float hb = (kk == 0) ? hv[b].x : (kk == 1) ? hv[b].y
                             : (kk == 2) ? hv[b].z : hv[b].w;
                    acc[b][0]  += hb * wz.x;  acc[b][1]  += hb * wz.y;
                    acc[b][2]  += hb * wz.z;  acc[b][3]  += hb * wz.w;
                    acc[b][4]  += hb * wr.x;  acc[b][5]  += hb * wr.y;
                    acc[b][6]  += hb * wr.z;  acc[b][7]  += hb * wr.w;
                    acc[b][8]  += hb * wh.x;  acc[b][9]  += hb * wh.y;
                    acc[b][10] += hb * wh.z;  acc[b][11] += hb * wh.w;
                }
            }
        }

        // warp reduction (butterfly) for each of the 48 partial sums
        #pragma unroll
        for (int b = 0; b < 4; b++)
            #pragma unroll
            for (int c = 0; c < 12; c++) {
                float v = acc[b][c];
                v += __shfl_xor_sync(0xffffffffu, v, 16);
                v += __shfl_xor_sync(0xffffffffu, v, 8);
                v += __shfl_xor_sync(0xffffffffu, v, 4);
                v += __shfl_xor_sync(0xffffffffu, v, 2);
                v += __shfl_xor_sync(0xffffffffu, v, 1);
                acc[b][c] = v;
            }

        if (l < 16) {
            float mz = acc[lb][uj]     + bz;
            float mr = acc[lb][4 + uj] + brr;
            float mh = acc[lb][8 + uj] + bh;
            const float* xwt = xw + ((size_t)t * B_ + gb) * G3;
            float xz = __ldg(xwt + gu);
            float xr = __ldg(xwt + U_ + gu);
            float xh = __ldg(xwt + 2 * U_ + gu);
            float hold = __ldcg(h + gb * U_ + gu);
            float z  = 1.f / (1.f + expf(-(xz + mz)));
            float r  = 1.f / (1.f + expf(-(xr + mr)));
            float hh = tanhf(xh + r * mh);
            float hnew = z * hold + (1.f - z) * hh;
            out[((size_t)t * B_ + gb) * U_ + gu] = hnew;
            __stcg(h + gb * U_ + gu, hnew + 0.1f * (hold - hnew));  // zoneout carry
        }
        __threadfence();
        grid_barrier(gridDim.x);
    }
}

// ---------------- fp32 tiled GEMM: C = rowmap(A0 + s1*A1 + s2*A2) @ W + bias --
// permA: A row index = (m%32)*1024 + m/32 (read x as [B,T,*] while producing [T,B,*])
// permC: C row index = (m%32)*1024 + m/32 (write [B,T,*] from [T,B,*] rows)
__global__ void __launch_bounds__(256) gemm_kernel(
    const float* __restrict__ A0, const float* __restrict__ A1,
    const float* __restrict__ A2, const float* __restrict__ avec,
    int ia1, int ia2,
    const float* __restrict__ W, const float* __restrict__ bias,
    float* __restrict__ C, int M, int N, int K, int permA, int permC)
{
    __shared__ float As[16][64];
    __shared__ float Bs[16][64];
    const int tid = threadIdx.x;
    const int bm = blockIdx.x * 64;
    const int bn = blockIdx.y * 64;

    const int ar = tid >> 2,  ak = (tid & 3)  << 2;   // A tile load coords
    const int br = tid >> 4,  bc = (tid & 15) << 2;   // B tile load coords
    const int tm = (tid >> 4) << 2, tn = (tid & 15) << 2;  // 4x4 microtile

    const float s1 = A1 ? avec[ia1] : 0.f;
    const float s2 = A2 ? avec[ia2] : 0.f;

    const int m_a = bm + ar;
    const size_t arow = permA ? ((size_t)(m_a & 31) * T_ + (m_a >> 5)) : (size_t)m_a;
    const float* Ap0 = A0 + arow * K + ak;
    const float* Ap1 = A1 ? (A1 + arow * K + ak) : (const float*)0;
    const float* Ap2 = A2 ? (A2 + arow * K + ak) : (const float*)0;
    const float* Wp  = W + (size_t)br * N + bn + bc;

    float acc[4][4];
    #pragma unroll
    for (int i = 0; i < 4; i++)
        #pragma unroll
        for (int j = 0; j < 4; j++) acc[i][j] = 0.f;

    for (int k0 = 0; k0 < K; k0 += 16) {
        float4 av = *(const float4*)(Ap0 + k0);
        if (A1) {
            float4 t1 = *(const float4*)(Ap1 + k0);
            av.x += s1 * t1.x; av.y += s1 * t1.y; av.z += s1 * t1.z; av.w += s1 * t1.w;
        }
        if (A2) {
            float4 t2 = *(const float4*)(Ap2 + k0);
            av.x += s2 * t2.x; av.y += s2 * t2.y; av.z += s2 * t2.z; av.w += s2 * t2.w;
        }
        As[ak + 0][ar] = av.x; As[ak + 1][ar] = av.y;
        As[ak + 2][ar] = av.z; As[ak + 3][ar] = av.w;

        *(float4*)&Bs[br][bc] = *(const float4*)(Wp + (size_t)k0 * N);
        __syncthreads();

        #pragma unroll
        for (int kk = 0; kk < 16; kk++) {
            float4 a4 = *(const float4*)&As[kk][tm];
            float4 b4 = *(const float4*)&Bs[kk][tn];
            float aa[4] = {a4.x, a4.y, a4.z, a4.w};
            float bb[4] = {b4.x, b4.y, b4.z, b4.w};
            #pragma unroll
            for (int i = 0; i < 4; i++)
                #pragma unroll
                for (int j = 0; j < 4; j++)
                    acc[i][j] += aa[i] * bb[j];
        }
        __syncthreads();
    }

    #pragma unroll
    for (int i = 0; i < 4; i++) {
        int m = bm + tm + i;
        size_t crow = permC ? ((size_t)(m & 31) * T_ + (m >> 5)) : (size_t)m;
        float* cp = C + crow * N + bn + tn;
        #pragma unroll
        for (int j = 0; j < 4; j++)
            cp[j] = acc[i][j] + bias[bn + tn + j];
    }
}

// ---------------- host orchestration -----------------------------------------
extern "C" void kernel_launch(void* const* d_in, const int* in_sizes, int n_in,
                              void* d_out, int out_size)
{
    const float* x   = (const float*)d_in[0];
    const float* k0  = (const float*)d_in[1];
    const float* r0  = (const float*)d_in[2];
    const float* b0  = (const float*)d_in[3];
    const float* ks  = (const float*)d_in[4];
    const float* rs  = (const float*)d_in[5];
    const float* bs  = (const float*)d_in[6];
    const float* h00 = (const float*)d_in[7];
    const float* h01 = (const float*)d_in[8];
    const float* h02 = (const float*)d_in[9];
    const float* a   = (const float*)d_in[10];
    const float* wd  = (const float*)d_in[11];
    const float* bd  = (const float*)d_in[12];

    float *xw, *out0, *p0, *p1, *h;
    cudaGetSymbolAddress((void**)&xw,   g_xw);
    cudaGetSymbolAddress((void**)&out0, g_out0);
    cudaGetSymbolAddress((void**)&p0,   g_pred0);
    cudaGetSymbolAddress((void**)&p1,   g_pred1);
    cudaGetSymbolAddress((void**)&h,    g_h);

    const int M = B_ * T_;
    dim3 gridW(M / 64, G3 / 64);   // 512 x 24
    dim3 gridF(M / 64, D_ / 64);   // 512 x 4

    // ---- layer 0: xw = x @ k0 + b_in (perm A: [B,T,D] -> rows of [T,B,*]) ----
    init_h_kernel<<<64, 256>>>(h, h00);
    gemm_kernel<<<gridW, 256>>>(x, 0, 0, a, 0, 0, k0, b0, xw, M, G3, D_, 1, 0);
    scan_kernel<<<NCTA_SCAN, 256>>>(r0, b0 + G3, xw, out0, h);

    // ---- layer 1: input = out0 ----
    init_h_kernel<<<64, 256>>>(h, h01);
    gemm_kernel<<<gridW, 256>>>(out0, 0, 0, a, 0, 0, ks, bs, xw, M, G3, U_, 0, 0);
    scan_kernel<<<NCTA_SCAN, 256>>>(rs, bs + G3, xw, p0, h);

    // ---- layer 2: input = out0 + a[0]*pred0 (fused into GEMM A-load) ----
    init_h_kernel<<<64, 256>>>(h, h02);
    gemm_kernel<<<gridW, 256>>>(out0, p0, 0, a, 0, 0, ks, bs, xw, M, G3, U_, 0, 0);
    scan_kernel<<<NCTA_SCAN, 256>>>(rs, bs + G3, xw, p1, h);

    // ---- final: (out0 + a[1]*pred0 + a[2]*pred1) @ wd + bd, write [B,T,D] ----
    gemm_kernel<<<gridF, 256>>>(out0, p0, p1, a, 1, 2, wd, bd,
                                (float*)d_out, M, D_, U_, 0, 1);
}

// round 3
// speedup vs baseline: 1.1543x; 1.1543x over previous
#include <cuda_runtime.h>
#include <math.h>

#define B_  32
#define T_  1024
#define D_  256
#define U_  512
#define G3  1536          // 3*U
#define NCTA_SCAN 128

typedef unsigned long long ull;

// packed fp32x2 FMA: d = a*b + d (elementwise on the two fp32 halves)
#define FMA2(d_, a_, b_) \
    asm("fma.rn.f32x2 %0, %1, %2, %3;" : "=l"(d_) : "l"(a_), "l"(b_), "l"(d_))
// splat a scalar float into both halves of a 64-bit packed reg
#define SPLAT2(d_, s_) \
    asm("mov.b64 %0, {%1, %1};" : "=l"(d_) : "r"(__float_as_uint(s_)))

// ---------------- scratch (device globals: allocation-free contract) ----------
__device__ float g_xw[(size_t)T_ * B_ * G3];     // [T,B,3U] gate pre-activations
__device__ float g_out0[(size_t)T_ * B_ * U_];   // layer-0 outputs [T,B,U]
__device__ float g_pred0[(size_t)T_ * B_ * U_];  // layer-1 outputs
__device__ float g_pred1[(size_t)T_ * B_ * U_];  // layer-2 outputs
__device__ float g_h[B_ * U_];                   // carried hidden state
__device__ unsigned g_bar_count = 0;
__device__ unsigned g_bar_gen   = 0;

// ---------------- grid-wide sense-reversing barrier (tid0-only fences) --------
__device__ __forceinline__ void grid_barrier(unsigned ncta) {
    __syncthreads();
    if (threadIdx.x == 0) {
        volatile unsigned* genp = &g_bar_gen;
        unsigned g = *genp;
        __threadfence();                       // release (cumulative w/ syncthreads)
        unsigned arrived = atomicAdd(&g_bar_count, 1u);
        if (arrived == ncta - 1u) {
            g_bar_count = 0;
            __threadfence();
            *genp = g + 1u;
        } else {
            while (*genp == g) { }
        }
        __threadfence();                       // acquire
    }
    __syncthreads();
}

// ---------------- init hidden state: h[b][u] = h0[u] --------------------------
__global__ void init_h_kernel(float* __restrict__ h, const float* __restrict__ h0) {
    int i = blockIdx.x * blockDim.x + threadIdx.x;
    if (i < B_ * U_) h[i] = h0[i & (U_ - 1)];
}

// ---------------- persistent GRU scan (f32x2 packed over k) ------------------
// 128 CTAs x 256 threads. CTA owns units u0..u0+3 (12 gate-cols, col-major in
// SMEM). Warp w -> batches 4w..4w+3. Lane l -> k in {4l+128*i2+0..3}.
__global__ void __launch_bounds__(256, 1) scan_kernel(
    const float* __restrict__ R,      // recurrent [U,3U]
    const float* __restrict__ brec,   // recurrent bias [3U]
    const float* __restrict__ xw,     // [T,B,3U]
    float* __restrict__ out,          // [T,B,U]
    float* __restrict__ h)            // [B,U] carried state (global)
{
    __shared__ float ws[12 * U_];     // [c][k] col-major: 24 KB, conflict-free LDS.128

    const int tid = threadIdx.x;
    const int u0  = blockIdx.x * 4;

    // Preload the 12 recurrent columns this CTA owns (one time).
    for (int idx = tid; idx < U_ * 12; idx += 256) {
        int k = idx / 12, c = idx - k * 12;
        int g = c >> 2, j = c & 3;
        ws[c * U_ + k] = R[(size_t)k * G3 + g * U_ + u0 + j];
    }
    __syncthreads();

    const int w  = tid >> 5, l = tid & 31;
    const int b0 = w * 4;
    const int lb = l >> 2, uj = l & 3;
    const int gb = b0 + lb;          // batch handled by this gate-lane
    const int gu = u0 + uj;          // global hidden index handled
    const bool act = (l < 16);
    float bz = 0.f, brr = 0.f, bh = 0.f;
    if (act) {
        bz  = brec[gu];
        brr = brec[U_ + gu];
        bh  = brec[2 * U_ + gu];
    }

    // prefetch xw for t=0  (FIX: include +gu offsets)
    float xz = 0.f, xr = 0.f, xh = 0.f;
    if (act) {
        const float* xwt = xw + (size_t)gb * G3;
        xz = __ldg(xwt + gu);
        xr = __ldg(xwt + U_ + gu);
        xh = __ldg(xwt + 2 * U_ + gu);
    }

    for (int t = 0; t < T_; t++) {
        float hold = act ? __ldcg(h + gb * U_ + gu) : 0.f;

        ull acc[4][12];
        #pragma unroll
        for (int b = 0; b < 4; b++)
            #pragma unroll
            for (int c = 0; c < 12; c++) acc[b][c] = 0ull;

        #pragma unroll
        for (int i2 = 0; i2 < 4; i2++) {
            const int ko = 4 * l + 128 * i2;
            ulonglong2 hq[4];
            #pragma unroll
            for (int b = 0; b < 4; b++)
                hq[b] = __ldcg((const ulonglong2*)(h + (b0 + b) * U_ + ko));
            #pragma unroll
            for (int c = 0; c < 12; c++) {
                ulonglong2 wq = *(const ulonglong2*)(ws + c * U_ + ko);
                #pragma unroll
                for (int b = 0; b < 4; b++) {
                    FMA2(acc[b][c], hq[b].x, wq.x);
                    FMA2(acc[b][c], hq[b].y, wq.y);
                }
            }
        }

        // horizontal add of packed halves, then 5-stage butterfly allreduce
        float accs[4][12];
        #pragma unroll
        for (int b = 0; b < 4; b++)
            #pragma unroll
            for (int c = 0; c < 12; c++) {
                float2 v = *reinterpret_cast<float2*>(&acc[b][c]);
                accs[b][c] = v.x + v.y;
            }
        #pragma unroll
        for (int s = 16; s >= 1; s >>= 1)
            #pragma unroll
            for (int b = 0; b < 4; b++)
                #pragma unroll
                for (int c = 0; c < 12; c++)
                    accs[b][c] += __shfl_xor_sync(0xffffffffu, accs[b][c], s);

        if (act) {
            float mz = accs[lb][uj]     + bz;
            float mr = accs[lb][4 + uj] + brr;
            float mh = accs[lb][8 + uj] + bh;
            float z  = 1.f / (1.f + expf(-(xz + mz)));
            float r  = 1.f / (1.f + expf(-(xr + mr)));
            float hh = tanhf(xh + r * mh);
            float hnew = z * hold + (1.f - z) * hh;
            out[((size_t)t * B_ + gb) * U_ + gu] = hnew;
            __stcg(h + gb * U_ + gu, hnew + 0.1f * (hold - hnew));  // zoneout
        }

        // prefetch next step's xw BEFORE the barrier (hides DRAM latency)
        if (act && t + 1 < T_) {
            const float* xwt = xw + ((size_t)(t + 1) * B_ + gb) * G3;
            xz = __ldg(xwt + gu);
            xr = __ldg(xwt + U_ + gu);
            xh = __ldg(xwt + 2 * U_ + gu);
        }
        grid_barrier(gridDim.x);
    }
}

// ---------------- fp32 tiled GEMM with f32x2 (packed over n) ------------------
// C = rowmap(A0 + s1*A1 + s2*A2) @ W + bias
// permA/permC: row index = (m%32)*1024 + m/32 ([B,T,*] <-> [T,B,*])
__global__ void __launch_bounds__(256) gemm_kernel(
    const float* __restrict__ A0, const float* __restrict__ A1,
    const float* __restrict__ A2, const float* __restrict__ avec,
    int ia1, int ia2,
    const float* __restrict__ W, const float* __restrict__ bias,
    float* __restrict__ C, int M, int N, int K, int permA, int permC)
{
    __shared__ float As[16][64];
    __shared__ float Bs[16][64];
    const int tid = threadIdx.x;
    const int bm = blockIdx.x * 64;
    const int bn = blockIdx.y * 64;

    const int ar = tid >> 2,  ak = (tid & 3)  << 2;   // A tile load coords
    const int br = tid >> 4,  bc = (tid & 15) << 2;   // B tile load coords
    const int tm = (tid >> 4) << 2, tn = (tid & 15) << 2;  // 4x4 microtile

    const float s1 = A1 ? avec[ia1] : 0.f;
    const float s2 = A2 ? avec[ia2] : 0.f;

    const int m_a = bm + ar;
    const size_t arow = permA ? ((size_t)(m_a & 31) * T_ + (m_a >> 5)) : (size_t)m_a;
    const float* Ap0 = A0 + arow * K + ak;
    const float* Ap1 = A1 ? (A1 + arow * K + ak) : (const float*)0;
    const float* Ap2 = A2 ? (A2 + arow * K + ak) : (const float*)0;
    const float* Wp  = W + (size_t)br * N + bn + bc;

    ull acc2[4][2];   // rows tm..tm+3, packed n-pairs (tn..tn+3)
    #pragma unroll
    for (int i = 0; i < 4; i++) { acc2[i][0] = 0ull; acc2[i][1] = 0ull; }

    for (int k0 = 0; k0 < K; k0 += 16) {
        float4 av = *(const float4*)(Ap0 + k0);
        if (A1) {
            float4 t1 = *(const float4*)(Ap1 + k0);
            av.x += s1 * t1.x; av.y += s1 * t1.y; av.z += s1 * t1.z; av.w += s1 * t1.w;
        }
        if (A2) {
            float4 t2 = *(const float4*)(Ap2 + k0);
            av.x += s2 * t2.x; av.y += s2 * t2.y; av.z += s2 * t2.z; av.w += s2 * t2.w;
        }
        As[ak + 0][ar] = av.x; As[ak + 1][ar] = av.y;
        As[ak + 2][ar] = av.z; As[ak + 3][ar] = av.w;

        *(float4*)&Bs[br][bc] = *(const float4*)(Wp + (size_t)k0 * N);
        __syncthreads();

        #pragma unroll
        for (int kk = 0; kk < 16; kk++) {
            float4 a4 = *(const float4*)&As[kk][tm];
            ulonglong2 b2 = *(const ulonglong2*)&Bs[kk][tn];
            ull as0, as1, as2, as3;
            SPLAT2(as0, a4.x); SPLAT2(as1, a4.y);
            SPLAT2(as2, a4.z); SPLAT2(as3, a4.w);
            FMA2(acc2[0][0], as0, b2.x); FMA2(acc2[0][1], as0, b2.y);
            FMA2(acc2[1][0], as1, b2.x); FMA2(acc2[1][1], as1, b2.y);
            FMA2(acc2[2][0], as2, b2.x); FMA2(acc2[2][1], as2, b2.y);
            FMA2(acc2[3][0], as3, b2.x); FMA2(acc2[3][1], as3, b2.y);
        }
        __syncthreads();
    }

    #pragma unroll
    for (int i = 0; i < 4; i++) {
        int m = bm + tm + i;
        size_t crow = permC ? ((size_t)(m & 31) * T_ + (m >> 5)) : (size_t)m;
        float* cp = C + crow * N + bn + tn;
        #pragma unroll
        for (int jp = 0; jp < 2; jp++) {
            float2 v = *reinterpret_cast<float2*>(&acc2[i][jp]);
            cp[2 * jp + 0] = v.x + bias[bn + tn + 2 * jp + 0];
            cp[2 * jp + 1] = v.y + bias[bn + tn + 2 * jp + 1];
        }
    }
}

// ---------------- host orchestration -----------------------------------------
extern "C" void kernel_launch(void* const* d_in, const int* in_sizes, int n_in,
                              void* d_out, int out_size)
{
    const float* x   = (const float*)d_in[0];
    const float* k0  = (const float*)d_in[1];
    const float* r0  = (const float*)d_in[2];
    const float* b0  = (const float*)d_in[3];
    const float* ks  = (const float*)d_in[4];
    const float* rs  = (const float*)d_in[5];
    const float* bs  = (const float*)d_in[6];
    const float* h00 = (const float*)d_in[7];
    const float* h01 = (const float*)d_in[8];
    const float* h02 = (const float*)d_in[9];
    const float* a   = (const float*)d_in[10];
    const float* wd  = (const float*)d_in[11];
    const float* bd  = (const float*)d_in[12];

    float *xw, *out0, *p0, *p1, *h;
    cudaGetSymbolAddress((void**)&xw,   g_xw);
    cudaGetSymbolAddress((void**)&out0, g_out0);
    cudaGetSymbolAddress((void**)&p0,   g_pred0);
    cudaGetSymbolAddress((void**)&p1,   g_pred1);
    cudaGetSymbolAddress((void**)&h,    g_h);

    const int M = B_ * T_;
    dim3 gridW(M / 64, G3 / 64);   // 512 x 24
    dim3 gridF(M / 64, D_ / 64);   // 512 x 4

    // ---- layer 0: xw = x @ k0 + b_in ----
    init_h_kernel<<<64, 256>>>(h, h00);
    gemm_kernel<<<gridW, 256>>>(x, 0, 0, a, 0, 0, k0, b0, xw, M, G3, D_, 1, 0);
    scan_kernel<<<NCTA_SCAN, 256>>>(r0, b0 + G3, xw, out0, h);

    // ---- layer 1: input = out0 ----
    init_h_kernel<<<64, 256>>>(h, h01);
    gemm_kernel<<<gridW, 256>>>(out0, 0, 0, a, 0, 0, ks, bs, xw, M, G3, U_, 0, 0);
    scan_kernel<<<NCTA_SCAN, 256>>>(rs, bs + G3, xw, p0, h);

    // ---- layer 2: input = out0 + a[0]*pred0 (fused into GEMM A-load) ----
    init_h_kernel<<<64, 256>>>(h, h02);
    gemm_kernel<<<gridW, 256>>>(out0, p0, 0, a, 0, 0, ks, bs, xw, M, G3, U_, 0, 0);
    scan_kernel<<<NCTA_SCAN, 256>>>(rs, bs + G3, xw, p1, h);

    // ---- final: (out0 + a[1]*pred0 + a[2]*pred1) @ wd + bd -> [B,T,D] ----
    gemm_kernel<<<gridF, 256>>>(out0, p0, p1, a, 1, 2, wd, bd,
                                (float*)d_out, M, D_, U_, 0, 1);
}